// round 13
// baseline (speedup 1.0000x reference)
#include <cuda_runtime.h>
#include <math.h>

// Problem constants
#define BATCH 4096
#define DIM   64

// Tiling: 128-thread CTA = 4 warps, ALL serving the SAME 4-row group.
// Warp h owns j-quarter [16h, 16h+16). Lane l owns comps i=l (A), i=l+32 (B).
// 1024 CTAs -> 4096 warps; ~95 regs -> 5 CTAs/SM (20 warps/SM resident).
#define R        4
#define THREADS  128
#define NBLOCKS  (BATCH / R)       // 1024

#define MAX_IT   50
#define DTOL     2e-3f
#define N_FINAL  1                 // accurate-tanh polish iterations

#define WPITCH 68   // W staging pitch (conflict-free strided LDS.128)

typedef unsigned long long u64;

__device__ __forceinline__ void upk(float& lo, float& hi, u64 v) {
    asm("mov.b64 {%0, %1}, %2;" : "=f"(lo), "=f"(hi) : "l"(v));
}
__device__ __forceinline__ void fma2(u64& d, u64 a, u64 b) {
    asm("fma.rn.f32x2 %0, %1, %2, %0;" : "+l"(d) : "l"(a), "l"(b));
}
__device__ __forceinline__ u64 add2(u64 a, u64 b) {
    u64 r; asm("add.rn.f32x2 %0, %1, %2;" : "=l"(r) : "l"(a), "l"(b)); return r;
}

// Fast hw tanh: 1 MUFU (residual error removed by contraction + polish).
__device__ __forceinline__ float tanh_fast(float a) {
    float t; asm("tanh.approx.f32 %0, %1;" : "=f"(t) : "f"(a)); return t;
}
// Accurate tanh (~1e-6): EX2 + Newton-refined reciprocal, fast-math-proof.
__device__ __forceinline__ float tanh_acc(float a) {
    float aa = fabsf(a);
    float e;
    asm("ex2.approx.ftz.f32 %0, %1;" : "=f"(e) : "f"(aa * -2.8853900817779268f));
    float d = 1.0f + e;
    float r = fmaf(-0.49043f, d, 1.4571f);
    r = r * (2.0f - d * r);
    r = r * (2.0f - d * r);
    return copysignf((1.0f - e) * r, a);
}

__global__ void __launch_bounds__(THREADS, 5)
tanh_fixed_point_kernel(const float* __restrict__ x,
                        const float* __restrict__ W,
                        float* __restrict__ out)
{
    __shared__ __align__(16) float  Wsh[DIM * WPITCH];   // one-time stage
    __shared__ __align__(16) float  zsh[R][DIM];         // z (redundant identical writes x4)
    // Partials: psh[pp][warp][rpair][lane] = float4(pA_{2rp}, pB_{2rp}, pA_{2rp+1}, pB_{2rp+1})
    __shared__ __align__(16) float4 psh[2][4][2][32];

    const int tid  = threadIdx.x;
    const int lane = tid & 31;
    const int h    = tid >> 5;     // j-quarter index = warp id

    // Stage W into shared (coalesced float4 loads)
    for (int v = tid; v < (DIM * DIM) / 4; v += THREADS) {
        int i = v >> 4;
        int k = v & 15;
        float4 f = reinterpret_cast<const float4*>(W)[v];
        *reinterpret_cast<float4*>(&Wsh[i * WPITCH + 4 * k]) = f;
    }
    __syncthreads();

    // W regs: my j-quarter [16h,16h+16) of rows i=lane (A), i=lane+32 (B),
    // packed consecutive-j pairs: 8 u64 per row = 32 regs total.
    const int jbase = h * 16;
    u64 wA[8], wB[8];
    {
        const ulonglong2* rowA = reinterpret_cast<const ulonglong2*>(&Wsh[lane * WPITCH + jbase]);
        const ulonglong2* rowB = reinterpret_cast<const ulonglong2*>(&Wsh[(lane + 32) * WPITCH + jbase]);
        #pragma unroll
        for (int q = 0; q < 4; q++) {
            ulonglong2 va = rowA[q];
            ulonglong2 vb = rowB[q];
            wA[2 * q] = va.x; wA[2 * q + 1] = va.y;
            wB[2 * q] = vb.x; wB[2 * q + 1] = vb.y;
        }
    }

    const int row0 = blockIdx.x * R;

    float xrA[R], xrB[R], zA[R], zB[R];
    #pragma unroll
    for (int r = 0; r < R; r++) {
        xrA[r] = x[(row0 + r) * DIM + lane];
        xrB[r] = x[(row0 + r) * DIM + lane + 32];
        zA[r]  = tanh_acc(xrA[r]);
        zB[r]  = tanh_acc(xrB[r]);
        zsh[r][lane]      = zA[r];   // all 4 warps write identical values
        zsh[r][lane + 32] = zB[r];
    }
    __syncthreads();

    int pp = 0;
    bool convPrev = false;   // delayed vote: conv of iter k voted inside iter k+1

    auto do_iter = [&](bool approx, bool vote) -> bool {
        // 8 independent packed chains (r x comp), depth 4.
        u64 aA[R], aB[R];
        #pragma unroll
        for (int r = 0; r < R; r++) {
            u64 zz; asm("mov.b64 %0, {%1, %1};" : "=l"(zz) : "f"(0.0f));
            aA[r] = zz; aB[r] = zz;
        }
        #pragma unroll
        for (int q2 = 0; q2 < 4; q2++) {
            #pragma unroll
            for (int r = 0; r < R; r++) {
                ulonglong2 zp =
                    (reinterpret_cast<const ulonglong2*>(zsh[r] + jbase))[q2];
                fma2(aA[r], wA[2 * q2],     zp.x);
                fma2(aA[r], wA[2 * q2 + 1], zp.y);
                fma2(aB[r], wB[2 * q2],     zp.x);
                fma2(aB[r], wB[2 * q2 + 1], zp.y);
            }
        }
        // My-quarter partials (pA,pB) per row; pack 2 rows per float4 store.
        float pA[R], pB[R];
        #pragma unroll
        for (int r = 0; r < R; r++) {
            float lo, hi;
            upk(lo, hi, aA[r]); pA[r] = lo + hi;
            upk(lo, hi, aB[r]); pB[r] = lo + hi;
        }
        #pragma unroll
        for (int rp = 0; rp < 2; rp++)
            psh[pp][h][rp][lane] = make_float4(pA[2 * rp], pB[2 * rp],
                                               pA[2 * rp + 1], pB[2 * rp + 1]);

        // Single block barrier: publishes partials AND votes previous conv.
        int allc = __syncthreads_and((vote && convPrev) ? 1 : 0);
        if (vote && allc) return true;          // uniform across block

        bool conv = true;
        #pragma unroll
        for (int rp = 0; rp < 2; rp++) {
            // Fixed-order reduction -> bitwise identical in all 4 warps.
            const u64* b0 = reinterpret_cast<const u64*>(&psh[pp][0][rp][lane]);
            const u64* b1 = reinterpret_cast<const u64*>(&psh[pp][1][rp][lane]);
            const u64* b2 = reinterpret_cast<const u64*>(&psh[pp][2][rp][lane]);
            const u64* b3 = reinterpret_cast<const u64*>(&psh[pp][3][rp][lane]);
            #pragma unroll
            for (int k = 0; k < 2; k++) {       // k: row within pair (float2 halves)
                int r = 2 * rp + k;
                u64 s = add2(add2(b0[k], b1[k]), add2(b2[k], b3[k]));
                float sA, sB; upk(sA, sB, s);
                float zlA = sA + xrA[r];
                float zlB = sB + xrB[r];
                float nA = approx ? tanh_fast(zlA) : tanh_acc(zlA);
                float nB = approx ? tanh_fast(zlB) : tanh_acc(zlB);
                conv = conv && (fabsf(nA - zA[r]) < DTOL) && (fabsf(nB - zB[r]) < DTOL);
                zA[r] = nA; zB[r] = nB;
                zsh[r][lane]      = nA;         // redundant identical writes
                zsh[r][lane + 32] = nB;
            }
        }
        convPrev = conv;
        pp ^= 1;
        return false;
    };

    // Phase 1: fast-tanh contraction with delayed block-wide vote
    for (int it = 0; it < MAX_IT; it++) {
        if (do_iter(true, true)) break;
    }
    // Phase 2: accurate-tanh polish (fixed, no vote)
    #pragma unroll
    for (int f = 0; f < N_FINAL; f++) (void)do_iter(false, false);

    // Warp h writes row h (values identical across warps)
    out[(row0 + h) * DIM + lane]      = zA[h];
    out[(row0 + h) * DIM + lane + 32] = zB[h];
}

extern "C" void kernel_launch(void* const* d_in, const int* in_sizes, int n_in,
                              void* d_out, int out_size)
{
    const float* x = (const float*)d_in[0];   // [4096, 64]
    const float* W = (const float*)d_in[1];   // [64, 64]
    float* out = (float*)d_out;               // [4096, 64]
    (void)in_sizes; (void)n_in; (void)out_size;

    tanh_fixed_point_kernel<<<NBLOCKS, THREADS>>>(x, W, out);
}

// round 15
// speedup vs baseline: 1.0964x; 1.0964x over previous
#include <cuda_runtime.h>
#include <math.h>

// Problem constants
#define BATCH 4096
#define DIM   64

// Tiling (R7 engine = best measured): lane owns comps i=lane, i=lane+32;
// R=4 rows per warp; WPB=2 warps per CTA (warps fully autonomous).
// 512 CTAs -> 1024 warps, 16 independent FMA2 chains/warp, ~230 regs.
#define R        4
#define WPB      2
#define THREADS  (WPB * 32)
#define ROWS_PER_BLOCK (R * WPB)                 // 8
#define NBLOCKS  (BATCH / ROWS_PER_BLOCK)        // 512

#define MAX_IT   50
#define DTOL     2e-3f
#define N_FINAL  2                 // accurate-tanh polish iterations

#define WPITCH 68   // W staging pitch (conflict-free strided LDS.128)

typedef unsigned long long u64;

__device__ __forceinline__ u64 pk(float lo, float hi) {
    u64 r; asm("mov.b64 %0, {%1, %2};" : "=l"(r) : "f"(lo), "f"(hi)); return r;
}
__device__ __forceinline__ void upk(float& lo, float& hi, u64 v) {
    asm("mov.b64 {%0, %1}, %2;" : "=f"(lo), "=f"(hi) : "l"(v));
}
__device__ __forceinline__ void fma2(u64& d, u64 a, u64 b) {
    asm("fma.rn.f32x2 %0, %1, %2, %0;" : "+l"(d) : "l"(a), "l"(b));
}

// Fast hw tanh: 1 MUFU, err ~6e-4 (offset removed by polish).
__device__ __forceinline__ float tanh_fast(float a) {
    float t; asm("tanh.approx.f32 %0, %1;" : "=f"(t) : "f"(a)); return t;
}
// Accurate tanh (~1e-6): EX2 + Newton-refined reciprocal, fast-math-proof.
__device__ __forceinline__ float tanh_acc(float a) {
    float aa = fabsf(a);
    float e;
    asm("ex2.approx.ftz.f32 %0, %1;" : "=f"(e) : "f"(aa * -2.8853900817779268f));
    float d = 1.0f + e;
    float r = fmaf(-0.49043f, d, 1.4571f);
    r = r * (2.0f - d * r);
    r = r * (2.0f - d * r);
    return copysignf((1.0f - e) * r, a);
}

__global__ void __launch_bounds__(THREADS)
tanh_fixed_point_kernel(const float* __restrict__ x,
                        const float* __restrict__ W,
                        float* __restrict__ out)
{
    __shared__ __align__(16) float Wsh[DIM * WPITCH];      // one-time stage
    __shared__ __align__(16) float zsh[WPB][R][DIM];       // per-warp z slices

    const int tid  = threadIdx.x;
    const int lane = tid & 31;
    const int warp = tid >> 5;

    // Coalesced one-time stage of W into shared
    for (int v = tid; v < (DIM * DIM) / 4; v += THREADS) {
        int i = v >> 4;
        int k = v & 15;
        float4 f = reinterpret_cast<const float4*>(W)[v];
        *reinterpret_cast<float4*>(&Wsh[i * WPITCH + 4 * k]) = f;
    }
    __syncthreads();

    // W rows i=lane, i=lane+32 -> registers, packed consecutive-j pairs
    u64 wA[32], wB[32];
    {
        const ulonglong2* rowA = reinterpret_cast<const ulonglong2*>(&Wsh[lane * WPITCH]);
        const ulonglong2* rowB = reinterpret_cast<const ulonglong2*>(&Wsh[(lane + 32) * WPITCH]);
        #pragma unroll
        for (int q = 0; q < 16; q++) {
            ulonglong2 va = rowA[q];
            ulonglong2 vb = rowB[q];
            wA[2 * q] = va.x; wA[2 * q + 1] = va.y;
            wB[2 * q] = vb.x; wB[2 * q + 1] = vb.y;
        }
    }

    const int row0 = blockIdx.x * ROWS_PER_BLOCK + warp * R;

    float xr[R][2], z[R][2], dprev[R][2];
    #pragma unroll
    for (int r = 0; r < R; r++) {
        xr[r][0] = x[(row0 + r) * DIM + lane];          // coalesced
        xr[r][1] = x[(row0 + r) * DIM + lane + 32];
        z[r][0]  = tanh_acc(xr[r][0]);
        z[r][1]  = tanh_acc(xr[r][1]);
        dprev[r][0] = 0.0f;
        dprev[r][1] = 0.0f;
    }

    // One Picard iteration over this warp's rows. Optionally applies
    // component-wise Aitken (guarded) and returns the convergence flag.
    auto do_iter = [&](bool approx, bool aitken) -> bool {
        #pragma unroll
        for (int r = 0; r < R; r++) {
            zsh[warp][r][lane]      = z[r][0];
            zsh[warp][r][lane + 32] = z[r][1];
        }
        __syncwarp();

        // 16 independent packed chains, depth 16
        u64 acc0[R][2], acc1[R][2];
        #pragma unroll
        for (int r = 0; r < R; r++) {
            acc0[r][0] = pk(xr[r][0], 0.0f);  acc1[r][0] = pk(0.0f, 0.0f);
            acc0[r][1] = pk(xr[r][1], 0.0f);  acc1[r][1] = pk(0.0f, 0.0f);
        }
        #pragma unroll
        for (int jq = 0; jq < 16; jq++) {
            #pragma unroll
            for (int r = 0; r < R; r++) {
                ulonglong2 zp = reinterpret_cast<const ulonglong2*>(zsh[warp][r])[jq];
                fma2(acc0[r][0], wA[2 * jq],     zp.x);
                fma2(acc1[r][0], wA[2 * jq + 1], zp.y);
                fma2(acc0[r][1], wB[2 * jq],     zp.x);
                fma2(acc1[r][1], wB[2 * jq + 1], zp.y);
            }
        }

        bool conv = true;
        #pragma unroll
        for (int r = 0; r < R; r++) {
            #pragma unroll
            for (int k = 0; k < 2; k++) {
                float a0, a1, b0, b1;
                upk(a0, a1, acc0[r][k]);
                upk(b0, b1, acc1[r][k]);
                float zl = (a0 + b0) + (a1 + b1);
                float n  = approx ? tanh_fast(zl) : tanh_acc(zl);
                float d2 = n - z[r][k];
                conv = conv && (fabsf(d2) < DTOL);
                float zn = n;
                if (aitken) {
                    // Aitken delta-squared: z* = n + d2^2/(d1-d2), guarded so
                    // the acceleration factor is bounded (skip noisy deltas).
                    float den = dprev[r][k] - d2;
                    if (fabsf(den) > 0.25f * fabsf(d2)) {
                        zn = fmaf(d2 * d2, __frcp_rn(den), n);
                        // clamp into tanh range for safety
                        zn = fminf(fmaxf(zn, -1.0f), 1.0f);
                    }
                }
                dprev[r][k] = d2;
                z[r][k] = zn;
            }
        }
        __syncwarp();   // reads done before next iteration's stores
        return conv;
    };

    // Phase 1: fast-tanh contraction, Aitken boosts at it==4 and it==8
    for (int it = 0; it < MAX_IT; it++) {
        bool conv = do_iter(true, (it == 4) || (it == 8));
        if (__all_sync(0xffffffffu, conv)) break;
    }
    // Phase 2: accurate-tanh polish (fixed count)
    #pragma unroll
    for (int f = 0; f < N_FINAL; f++) (void)do_iter(false, false);

    #pragma unroll
    for (int r = 0; r < R; r++) {
        out[(row0 + r) * DIM + lane]      = z[r][0];
        out[(row0 + r) * DIM + lane + 32] = z[r][1];
    }
}

extern "C" void kernel_launch(void* const* d_in, const int* in_sizes, int n_in,
                              void* d_out, int out_size)
{
    const float* x = (const float*)d_in[0];   // [4096, 64]
    const float* W = (const float*)d_in[1];   // [64, 64]
    float* out = (float*)d_out;               // [4096, 64]
    (void)in_sizes; (void)n_in; (void)out_size;

    tanh_fixed_point_kernel<<<NBLOCKS, THREADS>>>(x, W, out);
}

// round 16
// speedup vs baseline: 1.2530x; 1.1429x over previous
#include <cuda_runtime.h>
#include <math.h>

// Problem constants
#define BATCH 4096
#define DIM   64

// Tiling (R7 engine = best measured): lane owns comps i=lane, i=lane+32;
// R=4 rows per warp; WPB=2 autonomous warps per CTA.
// 512 CTAs -> 1024 warps, 16 independent FMA2 chains/warp, ~224 regs.
#define R        4
#define WPB      2
#define THREADS  (WPB * 32)
#define ROWS_PER_BLOCK (R * WPB)                 // 8
#define NBLOCKS  (BATCH / ROWS_PER_BLOCK)        // 512

#define MAX_IT   50
#define DTOL     2e-3f
#define VOTE_MIN 7                  // first iteration eligible to vote (odd its only)

#define WPITCH 68   // W staging pitch (conflict-free strided LDS.128)

typedef unsigned long long u64;

__device__ __forceinline__ u64 pk(float lo, float hi) {
    u64 r; asm("mov.b64 %0, {%1, %2};" : "=l"(r) : "f"(lo), "f"(hi)); return r;
}
__device__ __forceinline__ void upk(float& lo, float& hi, u64 v) {
    asm("mov.b64 {%0, %1}, %2;" : "=f"(lo), "=f"(hi) : "l"(v));
}
__device__ __forceinline__ void fma2(u64& d, u64 a, u64 b) {
    asm("fma.rn.f32x2 %0, %1, %2, %0;" : "+l"(d) : "l"(a), "l"(b));
}

// Fast hw tanh: single MUFU instruction (err ~6e-4; removed by polish).
__device__ __forceinline__ float tanh_fast(float a) {
    float t; asm("tanh.approx.f32 %0, %1;" : "=f"(t) : "f"(a)); return t;
}
// Accurate tanh (~1e-6): EX2 + Newton-refined reciprocal, fast-math-proof.
__device__ __forceinline__ float tanh_acc(float a) {
    float aa = fabsf(a);
    float e;
    asm("ex2.approx.ftz.f32 %0, %1;" : "=f"(e) : "f"(aa * -2.8853900817779268f));
    float d = 1.0f + e;
    float r = fmaf(-0.49043f, d, 1.4571f);
    r = r * (2.0f - d * r);
    r = r * (2.0f - d * r);
    return copysignf((1.0f - e) * r, a);
}

__global__ void __launch_bounds__(THREADS)
tanh_fixed_point_kernel(const float* __restrict__ x,
                        const float* __restrict__ W,
                        float* __restrict__ out)
{
    __shared__ __align__(16) float Wsh[DIM * WPITCH];      // one-time stage
    __shared__ __align__(16) float zsh[WPB][R][DIM];       // per-warp z slices

    const int tid  = threadIdx.x;
    const int lane = tid & 31;
    const int warp = tid >> 5;

    // Coalesced one-time stage of W into shared
    for (int v = tid; v < (DIM * DIM) / 4; v += THREADS) {
        int i = v >> 4;
        int k = v & 15;
        float4 f = reinterpret_cast<const float4*>(W)[v];
        *reinterpret_cast<float4*>(&Wsh[i * WPITCH + 4 * k]) = f;
    }
    __syncthreads();

    // W rows i=lane, i=lane+32 -> registers, packed consecutive-j pairs
    u64 wA[32], wB[32];
    {
        const ulonglong2* rowA = reinterpret_cast<const ulonglong2*>(&Wsh[lane * WPITCH]);
        const ulonglong2* rowB = reinterpret_cast<const ulonglong2*>(&Wsh[(lane + 32) * WPITCH]);
        #pragma unroll
        for (int q = 0; q < 16; q++) {
            ulonglong2 va = rowA[q];
            ulonglong2 vb = rowB[q];
            wA[2 * q] = va.x; wA[2 * q + 1] = va.y;
            wB[2 * q] = vb.x; wB[2 * q + 1] = vb.y;
        }
    }

    const int row0 = blockIdx.x * ROWS_PER_BLOCK + warp * R;

    float xr[R][2], z[R][2];
    #pragma unroll
    for (int r = 0; r < R; r++) {
        xr[r][0] = x[(row0 + r) * DIM + lane];          // coalesced
        xr[r][1] = x[(row0 + r) * DIM + lane + 32];
        z[r][0]  = tanh_acc(xr[r][0]);
        z[r][1]  = tanh_acc(xr[r][1]);
    }

    // One Picard iteration. check=false skips all convergence arithmetic.
    auto do_iter = [&](bool approx, bool check) -> bool {
        #pragma unroll
        for (int r = 0; r < R; r++) {
            zsh[warp][r][lane]      = z[r][0];
            zsh[warp][r][lane + 32] = z[r][1];
        }
        __syncwarp();

        // 16 independent packed chains, depth 16
        u64 acc0[R][2], acc1[R][2];
        #pragma unroll
        for (int r = 0; r < R; r++) {
            acc0[r][0] = pk(xr[r][0], 0.0f);  acc1[r][0] = pk(0.0f, 0.0f);
            acc0[r][1] = pk(xr[r][1], 0.0f);  acc1[r][1] = pk(0.0f, 0.0f);
        }
        #pragma unroll
        for (int jq = 0; jq < 16; jq++) {
            #pragma unroll
            for (int r = 0; r < R; r++) {
                ulonglong2 zp = reinterpret_cast<const ulonglong2*>(zsh[warp][r])[jq];
                fma2(acc0[r][0], wA[2 * jq],     zp.x);
                fma2(acc1[r][0], wA[2 * jq + 1], zp.y);
                fma2(acc0[r][1], wB[2 * jq],     zp.x);
                fma2(acc1[r][1], wB[2 * jq + 1], zp.y);
            }
        }

        bool conv = true;
        #pragma unroll
        for (int r = 0; r < R; r++) {
            #pragma unroll
            for (int k = 0; k < 2; k++) {
                float a0, a1, b0, b1;
                upk(a0, a1, acc0[r][k]);
                upk(b0, b1, acc1[r][k]);
                float zl = (a0 + b0) + (a1 + b1);
                float n  = approx ? tanh_fast(zl) : tanh_acc(zl);
                if (check)
                    conv = conv && (fabsf(n - z[r][k]) < DTOL);
                z[r][k] = n;
            }
        }
        __syncwarp();   // reads done before next iteration's stores
        return conv;
    };

    // Phase 1: fast-tanh contraction; vote only on odd iterations >= VOTE_MIN
    for (int it = 0; it < MAX_IT; it++) {
        bool doCheck = (it >= VOTE_MIN) && (it & 1);
        bool conv = do_iter(true, doCheck);
        if (doCheck && __all_sync(0xffffffffu, conv)) break;
    }
    // Phase 2: one accurate-tanh polish iteration (no check)
    (void)do_iter(false, false);

    #pragma unroll
    for (int r = 0; r < R; r++) {
        out[(row0 + r) * DIM + lane]      = z[r][0];
        out[(row0 + r) * DIM + lane + 32] = z[r][1];
    }
}

extern "C" void kernel_launch(void* const* d_in, const int* in_sizes, int n_in,
                              void* d_out, int out_size)
{
    const float* x = (const float*)d_in[0];   // [4096, 64]
    const float* W = (const float*)d_in[1];   // [64, 64]
    float* out = (float*)d_out;               // [4096, 64]
    (void)in_sizes; (void)n_in; (void)out_size;

    tanh_fixed_point_kernel<<<NBLOCKS, THREADS>>>(x, W, out);
}

// round 17
// speedup vs baseline: 1.2595x; 1.0052x over previous
#include <cuda_runtime.h>
#include <math.h>

// Problem constants
#define BATCH 4096
#define DIM   64

// Tiling: lane owns comps i=lane (A), i=lane+32 (B); R=2 rows per warp;
// WPB=4 autonomous warps per CTA (covers all 4 SMSPs).
// 512 CTAs -> 2048 warps; ~195 regs -> ~10 warps/SM resident.
// Core loop: explicit 2-stage prefetch pipeline hides LDS latency.
#define R        2
#define WPB      4
#define THREADS  (WPB * 32)
#define ROWS_PER_BLOCK (R * WPB)                 // 8
#define NBLOCKS  (BATCH / ROWS_PER_BLOCK)        // 512

#define MAX_IT   50
#define DTOL     6e-3f
#define VOTE_MIN 4

#define WPITCH 68   // W staging pitch (conflict-free strided LDS.128)

typedef unsigned long long u64;

__device__ __forceinline__ u64 pk(float lo, float hi) {
    u64 r; asm("mov.b64 %0, {%1, %2};" : "=l"(r) : "f"(lo), "f"(hi)); return r;
}
__device__ __forceinline__ void upk(float& lo, float& hi, u64 v) {
    asm("mov.b64 {%0, %1}, %2;" : "=f"(lo), "=f"(hi) : "l"(v));
}
__device__ __forceinline__ void fma2(u64& d, u64 a, u64 b) {
    asm("fma.rn.f32x2 %0, %1, %2, %0;" : "+l"(d) : "l"(a), "l"(b));
}

// Fast hw tanh: single MUFU (err ~6e-4; removed by accurate polish).
__device__ __forceinline__ float tanh_fast(float a) {
    float t; asm("tanh.approx.f32 %0, %1;" : "=f"(t) : "f"(a)); return t;
}
// Accurate tanh (~1e-6): EX2 + Newton-refined reciprocal, fast-math-proof.
__device__ __forceinline__ float tanh_acc(float a) {
    float aa = fabsf(a);
    float e;
    asm("ex2.approx.ftz.f32 %0, %1;" : "=f"(e) : "f"(aa * -2.8853900817779268f));
    float d = 1.0f + e;
    float r = fmaf(-0.49043f, d, 1.4571f);
    r = r * (2.0f - d * r);
    r = r * (2.0f - d * r);
    return copysignf((1.0f - e) * r, a);
}

__global__ void __launch_bounds__(THREADS)
tanh_fixed_point_kernel(const float* __restrict__ x,
                        const float* __restrict__ W,
                        float* __restrict__ out)
{
    __shared__ __align__(16) float Wsh[DIM * WPITCH];      // one-time stage
    __shared__ __align__(16) float zsh[WPB][R][DIM];       // per-warp z slices

    const int tid  = threadIdx.x;
    const int lane = tid & 31;
    const int warp = tid >> 5;

    // Coalesced one-time stage of W into shared
    for (int v = tid; v < (DIM * DIM) / 4; v += THREADS) {
        int i = v >> 4;
        int k = v & 15;
        float4 f = reinterpret_cast<const float4*>(W)[v];
        *reinterpret_cast<float4*>(&Wsh[i * WPITCH + 4 * k]) = f;
    }
    __syncthreads();

    // W rows i=lane, i=lane+32 -> registers, packed consecutive-j pairs
    u64 wA[32], wB[32];
    {
        const ulonglong2* rowA = reinterpret_cast<const ulonglong2*>(&Wsh[lane * WPITCH]);
        const ulonglong2* rowB = reinterpret_cast<const ulonglong2*>(&Wsh[(lane + 32) * WPITCH]);
        #pragma unroll
        for (int q = 0; q < 16; q++) {
            ulonglong2 va = rowA[q];
            ulonglong2 vb = rowB[q];
            wA[2 * q] = va.x; wA[2 * q + 1] = va.y;
            wB[2 * q] = vb.x; wB[2 * q + 1] = vb.y;
        }
    }

    const int row0 = blockIdx.x * ROWS_PER_BLOCK + warp * R;

    float xr[R][2], z[R][2];
    #pragma unroll
    for (int r = 0; r < R; r++) {
        xr[r][0] = x[(row0 + r) * DIM + lane];          // coalesced
        xr[r][1] = x[(row0 + r) * DIM + lane + 32];
        z[r][0]  = tanh_fast(xr[r][0]);                 // cheap z0 (error contracts)
        z[r][1]  = tanh_fast(xr[r][1]);
    }

    // One Picard iteration with software-pipelined z loads.
    auto do_iter = [&](bool approx, bool check) -> bool {
        #pragma unroll
        for (int r = 0; r < R; r++) {
            zsh[warp][r][lane]      = z[r][0];
            zsh[warp][r][lane + 32] = z[r][1];
        }
        __syncwarp();

        const ulonglong2* Z0 = reinterpret_cast<const ulonglong2*>(zsh[warp][0]);
        const ulonglong2* Z1 = reinterpret_cast<const ulonglong2*>(zsh[warp][1]);

        // 8 independent packed chains, depth 16
        u64 acc0[R][2], acc1[R][2];
        #pragma unroll
        for (int r = 0; r < R; r++) {
            acc0[r][0] = pk(xr[r][0], 0.0f);  acc1[r][0] = pk(0.0f, 0.0f);
            acc0[r][1] = pk(xr[r][1], 0.0f);  acc1[r][1] = pk(0.0f, 0.0f);
        }

        // Pipeline: chunk c = ulonglong2 indices {2c, 2c+1} of both rows.
        // zb[buf][row][k]; prefetch chunk c+1 while FMA-ing chunk c.
        ulonglong2 zb[2][R][2];
        #pragma unroll
        for (int k = 0; k < 2; k++) { zb[0][0][k] = Z0[k]; zb[0][1][k] = Z1[k]; }

        #pragma unroll
        for (int c = 0; c < 8; c++) {
            const int buf = c & 1;
            if (c < 7) {                    // prefetch next chunk (4 LDS.128)
                #pragma unroll
                for (int k = 0; k < 2; k++) {
                    zb[buf ^ 1][0][k] = Z0[2 * (c + 1) + k];
                    zb[buf ^ 1][1][k] = Z1[2 * (c + 1) + k];
                }
            }
            #pragma unroll
            for (int r = 0; r < R; r++) {
                #pragma unroll
                for (int k = 0; k < 2; k++) {
                    const int q = 2 * c + k;          // ulonglong2 index
                    ulonglong2 zp = zb[buf][r][k];
                    fma2(acc0[r][0], wA[2 * q],     zp.x);
                    fma2(acc1[r][0], wA[2 * q + 1], zp.y);
                    fma2(acc0[r][1], wB[2 * q],     zp.x);
                    fma2(acc1[r][1], wB[2 * q + 1], zp.y);
                }
            }
        }

        bool conv = true;
        #pragma unroll
        for (int r = 0; r < R; r++) {
            #pragma unroll
            for (int k = 0; k < 2; k++) {
                float a0, a1, b0, b1;
                upk(a0, a1, acc0[r][k]);
                upk(b0, b1, acc1[r][k]);
                float zl = (a0 + b0) + (a1 + b1);
                float n  = approx ? tanh_fast(zl) : tanh_acc(zl);
                if (check)
                    conv = conv && (fabsf(n - z[r][k]) < DTOL);
                z[r][k] = n;
            }
        }
        __syncwarp();   // reads done before next iteration's stores
        return conv;
    };

    // Phase 1: fast-tanh contraction; vote every iteration from VOTE_MIN
    for (int it = 0; it < MAX_IT; it++) {
        bool doCheck = (it >= VOTE_MIN);
        bool conv = do_iter(true, doCheck);
        if (doCheck && __all_sync(0xffffffffu, conv)) break;
    }
    // Phase 2: one accurate-tanh polish iteration
    (void)do_iter(false, false);

    #pragma unroll
    for (int r = 0; r < R; r++) {
        out[(row0 + r) * DIM + lane]      = z[r][0];
        out[(row0 + r) * DIM + lane + 32] = z[r][1];
    }
}

extern "C" void kernel_launch(void* const* d_in, const int* in_sizes, int n_in,
                              void* d_out, int out_size)
{
    const float* x = (const float*)d_in[0];   // [4096, 64]
    const float* W = (const float*)d_in[1];   // [64, 64]
    float* out = (float*)d_out;               // [4096, 64]
    (void)in_sizes; (void)n_in; (void)out_size;

    tanh_fixed_point_kernel<<<NBLOCKS, THREADS>>>(x, W, out);
}